// round 3
// baseline (speedup 1.0000x reference)
#include <cuda_runtime.h>
#include <cstdint>

// CompressedHE: per-channel histogram equalization.
// x: [16,3,1024,1024] fp32 in [0,1)  ->  out same shape fp32.
// 48 channels of 1M pixels each.

#define NCH     48
#define HW      (1 << 20)          // pixels per channel
#define BPC     32                 // blocks per channel (streaming kernels)
#define CHUNK   (HW / BPC)         // 32768 pixels per block
#define THREADS 256
#define NWARP   (THREADS / 32)

// Scratch (device globals — no allocation allowed in kernel_launch).
__device__ int          g_hist[NCH * 256];
__device__ float        g_lut [NCH * 256];
__device__ unsigned int g_vals[NCH * HW / 4];   // 4 packed u8 bins per word (48 MiB)

__global__ void zero_hist_kernel() {
    int i = blockIdx.x * blockDim.x + threadIdx.x;
    if (i < NCH * 256) g_hist[i] = 0;
}

// Histogram WITHOUT per-pixel smem atomics: per 32 pixels (one per lane),
// __match_any_sync groups equal bins, the group leader does a non-atomic
// read-modify-write into a warp-private smem histogram. Warp-private copies
// mean no cross-warp races; match_any converges the warp each step and
// __syncwarp orders the RMW against the next step's reads.
__global__ void __launch_bounds__(THREADS)
hist_kernel(const float4* __restrict__ x) {
    const int chan = blockIdx.x >> 5;        // / BPC
    const int blk  = blockIdx.x & (BPC - 1);

    __shared__ int sh[NWARP * 256];          // 8 warp-private histograms (8 KB)
    #pragma unroll
    for (int j = threadIdx.x; j < NWARP * 256; j += THREADS) sh[j] = 0;
    __syncthreads();

    const int lane = threadIdx.x & 31;
    int* __restrict__ hw_ = &sh[(threadIdx.x >> 5) * 256];

    const size_t base = (size_t)chan * (HW / 4) + (size_t)blk * (CHUNK / 4);
    const float4* __restrict__ p = x + base;
    unsigned int* __restrict__ q = g_vals + base;

    #pragma unroll 4
    for (int i = threadIdx.x; i < CHUNK / 4; i += THREADS) {
        float4 v = p[i];
        // Truncation toward zero, identical to jnp astype(int32) after *255.0 (fp32).
        int b0 = min(max((int)(v.x * 255.0f), 0), 255);
        int b1 = min(max((int)(v.y * 255.0f), 0), 255);
        int b2 = min(max((int)(v.z * 255.0f), 0), 255);
        int b3 = min(max((int)(v.w * 255.0f), 0), 255);
        unsigned pack = (unsigned)b0 | ((unsigned)b1 << 8) |
                        ((unsigned)b2 << 16) | ((unsigned)b3 << 24);
        q[i] = pack;

        #pragma unroll
        for (int k = 0; k < 4; k++) {
            int b = (pack >> (8 * k)) & 255;
            unsigned mask = __match_any_sync(0xffffffffu, b);
            int leader = __ffs(mask) - 1;
            if (lane == leader) hw_[b] += __popc(mask);
            __syncwarp();
        }
    }
    __syncthreads();

    int t = threadIdx.x;
    int s = 0;
    #pragma unroll
    for (int w = 0; w < NWARP; w++) s += sh[w * 256 + t];
    if (s) atomicAdd(&g_hist[chan * 256 + t], s);
}

// One block per channel: find last occupied bin, shfl-based inclusive scan,
// build the shifted-cumsum LUT pre-divided by 255.
__global__ void __launch_bounds__(256)
lut_kernel() {
    const int c = blockIdx.x;
    const int t = threadIdx.x;
    const int lane = t & 31, wid = t >> 5;

    __shared__ int sh_h[256];
    __shared__ int sh_r[256];
    __shared__ int s_wsum[8];

    int h = g_hist[c * 256 + t];
    sh_h[t] = h;
    sh_r[t] = (h > 0) ? t : -1;
    __syncthreads();

    // Max-reduce for last occupied bin index.
    #pragma unroll
    for (int s = 128; s > 0; s >>= 1) {
        if (t < s) sh_r[t] = max(sh_r[t], sh_r[t + s]);
        __syncthreads();
    }
    const int last_cnt = sh_h[sh_r[0]];
    const int step = (HW - last_cnt) / 255;   // sum(hist) == HW always

    // Inclusive scan of hist (warp shfl scan + warp-sum scan).
    int v = h;
    #pragma unroll
    for (int d = 1; d < 32; d <<= 1) {
        int n = __shfl_up_sync(0xffffffffu, v, d);
        if (lane >= d) v += n;
    }
    if (lane == 31) s_wsum[wid] = v;
    __syncthreads();
    if (wid == 0 && lane < 8) {
        int wv = s_wsum[lane];
        #pragma unroll
        for (int d = 1; d < 8; d <<= 1) {
            int n = __shfl_up_sync(0xffu, wv, d);
            if (lane >= d) wv += n;
        }
        s_wsum[lane] = wv;
    }
    __syncthreads();
    int incl = v + (wid ? s_wsum[wid - 1] : 0);
    int excl = incl - h;                      // cum[b-1] (shifted cumsum)

    float outv;
    if (step == 0) {
        outv = (float)t;                      // pass quantized value through
    } else {
        int l = (excl + (step >> 1)) / step;  // lut = (cum_prev + step//2)//step
        outv = (float)min(l, 255);            // clip (lower bound automatic)
    }
    g_lut[c * 256 + t] = outv * (1.0f / 255.0f);
}

// Apply: 32-way replicated LUT so slut[bin*32+lane] hits bank==lane (no
// conflicts). u32 load = 4 pixels, float4 coalesced store.
__global__ void __launch_bounds__(THREADS)
apply_kernel(float4* __restrict__ out) {
    const int chan = blockIdx.x >> 5;
    const int blk  = blockIdx.x & (BPC - 1);
    const int lane = threadIdx.x & 31;

    __shared__ float slut[256 * 32];          // 32 KB replicated LUT
    const float* __restrict__ lutc = &g_lut[chan * 256];
    #pragma unroll
    for (int j = threadIdx.x; j < 256 * 32; j += THREADS)
        slut[j] = __ldg(&lutc[j >> 5]);
    __syncthreads();

    const size_t base = (size_t)chan * (HW / 4) + (size_t)blk * (CHUNK / 4);
    const unsigned int* __restrict__ q = g_vals + base;
    float4* __restrict__ o = out + base;

    #pragma unroll 8
    for (int i = threadIdx.x; i < CHUNK / 4; i += THREADS) {
        unsigned w = q[i];
        float4 r;
        r.x = slut[((w       & 255u) << 5) + lane];
        r.y = slut[(((w >> 8)  & 255u) << 5) + lane];
        r.z = slut[(((w >> 16) & 255u) << 5) + lane];
        r.w = slut[((w >> 24)          << 5) + lane];
        o[i] = r;
    }
}

extern "C" void kernel_launch(void* const* d_in, const int* in_sizes, int n_in,
                              void* d_out, int out_size) {
    const float4* x = (const float4*)d_in[0];
    float4* out = (float4*)d_out;

    zero_hist_kernel<<<(NCH * 256 + 255) / 256, 256>>>();
    hist_kernel<<<NCH * BPC, THREADS>>>(x);
    lut_kernel<<<NCH, 256>>>();
    apply_kernel<<<NCH * BPC, THREADS>>>(out);
}